// round 13
// baseline (speedup 1.0000x reference)
#include <cuda_runtime.h>
#include <cuda_fp16.h>
#include <math.h>
#include <stdint.h>

// Problem constants
#define Bb   4
#define SS   4096
#define HH   2048
#define DFFC 8192
#define BSZ  (Bb*SS)          // 16384 tokens
#define EPS_F 1e-5f

// ---------------- scratch (device globals; no allocation allowed) ----------
__device__ float g_logits[BSZ];
__device__ float g_r1[BSZ];
__device__ float g_thr[Bb];
__device__ int   g_sel[BSZ];
__device__ int   g_nsel;
__device__ float g_r2[BSZ];
__device__ float g_ssqp[(size_t)BSZ*64];      // per-(nCTA,warp) partial ssq of res

__device__ __half g_xh  [(size_t)BSZ*HH];     // x rounded to fp16
__device__ __half g_wvh [(size_t)HH*HH];      // n1w[m]*Wv fp16        [m][k]
__device__ __half g_woT [(size_t)HH*HH];      // Wo^T fp16             [n][k]
__device__ __half g_WcT [(size_t)HH*HH];      // Wcomb^T fp16          [n][k]
__device__ __half g_wgT [(size_t)DFFC*HH];    // (diag(n2w)*w_gate)^T  [n][k]
__device__ __half g_wuT [(size_t)DFFC*HH];    // (diag(n2w)*w_up)^T    [n][k]
__device__ __half g_wdT [(size_t)HH*DFFC];    // w_down^T fp16         [n][k]
__device__ float  g_res [(size_t)BSZ*HH];     // residual fp32 (selected order)
__device__ __half g_resh[(size_t)BSZ*HH];     // residual fp16
__device__ __half g_hbuf[(size_t)BSZ*DFFC];   // silu(gate) then h (fp16)

// ============================ PTX helpers ==================================
__device__ __forceinline__ uint32_t smem_to_u32(const void* p){
    uint32_t a;
    asm("{ .reg .u64 t; cvta.to.shared.u64 t, %1; cvt.u32.u64 %0, t; }" : "=r"(a) : "l"(p));
    return a;
}
__device__ __forceinline__ void cp16(uint32_t s, const void* g){
    asm volatile("cp.async.cg.shared.global [%0], [%1], 16;" :: "r"(s), "l"(g));
}
#define CP_COMMIT() asm volatile("cp.async.commit_group;" ::: "memory")
#define CP_WAIT2()  asm volatile("cp.async.wait_group 2;" ::: "memory")
#define CP_WAIT1()  asm volatile("cp.async.wait_group 1;" ::: "memory")
#define CP_WAIT0()  asm volatile("cp.async.wait_group 0;" ::: "memory")

#define LDSM4(r, addr) \
    asm volatile("ldmatrix.sync.aligned.m8n8.x4.shared.b16 {%0,%1,%2,%3}, [%4];" \
        : "=r"((r)[0]), "=r"((r)[1]), "=r"((r)[2]), "=r"((r)[3]) : "r"(addr))

__device__ __forceinline__ void mma16n8k16(float* c, const uint32_t* a, const uint32_t* b){
    asm volatile("mma.sync.aligned.m16n8k16.row.col.f32.f16.f16.f32 "
        "{%0,%1,%2,%3},{%4,%5,%6,%7},{%8,%9},{%0,%1,%2,%3};"
        : "+f"(c[0]), "+f"(c[1]), "+f"(c[2]), "+f"(c[3])
        : "r"(a[0]), "r"(a[1]), "r"(a[2]), "r"(a[3]), "r"(b[0]), "r"(b[1]));
}

// ===================== GEMM mainloop (128x128, K-stage 32 halves) ==========
// 256 threads = 8 warps in 2x4 (m x n); warp tile 64x32; acc[4 mtile][4 ntile][4]
// SMEM per stage block (20480B): A rows 128 x 80B at [0,10240), B at [10240,20480).
// 80B row stride -> ldmatrix 8-row fetches hit 32 distinct banks, conflict-free.
// 4-stage cp.async pipeline (power-of-two: s&3 indexing), ONE sync/stage,
// tail-graded wait_group.
#define STAGEB  20480
#define NSTAGE  4
#define SMEM_BYTES (NSTAGE*STAGEB)

__device__ __forceinline__ void gemm_ml(float (&acc)[4][4][4],
        const __half* aP, const __half* bP, int nK32,
        uint32_t sb, int tid)
{
    int lane = tid & 31;
    int mW = (tid >> 7) * 64;
    int nW = ((tid >> 5) & 3) * 32;
    uint32_t cpA = sb + (tid >> 1)*80 + (tid & 1)*32;
    uint32_t cpB = cpA + 10240;
    uint32_t aoff = (uint32_t)(mW + (lane & 7) + ((lane >> 3) & 1)*8)*80 + (lane >> 4)*16;
    uint32_t boff = 10240u + (uint32_t)(nW + ((lane >> 4) & 1)*8 + (lane & 7))*80
                          + ((lane >> 3) & 1)*16;

    #pragma unroll
    for (int s = 0; s < 3; s++){
        uint32_t off = s*STAGEB;
        const __half* an = aP + s*32;
        const __half* bn = bP + s*32;
        cp16(cpA + off, an); cp16(cpA + off + 16, an + 8);
        cp16(cpB + off, bn); cp16(cpB + off + 16, bn + 8);
        CP_COMMIT();
    }

    #pragma unroll 1
    for (int s = 0; s < nK32; s++){
        if (s + 2 < nK32) CP_WAIT2();
        else if (s + 1 < nK32) CP_WAIT1();
        else CP_WAIT0();
        __syncthreads();
        if (s + 3 < nK32){
            uint32_t off = ((uint32_t)(s + 3) & 3)*STAGEB;
            const __half* an = aP + (s + 3)*32;
            const __half* bn = bP + (s + 3)*32;
            cp16(cpA + off, an); cp16(cpA + off + 16, an + 8);
            cp16(cpB + off, bn); cp16(cpB + off + 16, bn + 8);
            CP_COMMIT();
        }
        uint32_t st = ((uint32_t)s & 3)*STAGEB;
        uint32_t smA = sb + st + aoff;
        uint32_t smB = sb + st + boff;
        #pragma unroll
        for (int step = 0; step < 2; step++){
            uint32_t a[4][4], b[2][4];
            #pragma unroll
            for (int i = 0; i < 4; i++) LDSM4(a[i], smA + i*1280 + step*32);
            #pragma unroll
            for (int p = 0; p < 2; p++) LDSM4(b[p], smB + p*1280 + step*32);
            #pragma unroll
            for (int i = 0; i < 4; i++)
                #pragma unroll
                for (int j = 0; j < 4; j++)
                    mma16n8k16(acc[i][j], a[i], &b[j >> 1][(j & 1)*2]);
        }
    }
}

#define GEMM_PROLOG() \
    extern __shared__ float smf[]; \
    uint32_t sb = smem_to_u32(smf); \
    int tid = threadIdx.x; \
    int row = tid >> 1, h16 = (tid & 1) * 16; \
    float acc[4][4][4]; \
    _Pragma("unroll") for (int i = 0; i < 4; i++) \
    _Pragma("unroll") for (int j = 0; j < 4; j++) \
    _Pragma("unroll") for (int q = 0; q < 4; q++) acc[i][j][q] = 0.f;

#define EPI_VARS() \
    int lane = tid & 31; \
    int mB = (tid >> 7) * 64; \
    int nB = ((tid >> 5) & 3) * 32;

// =========================== small kernels =================================
// fused: router logits (fp32 Kahan) + rms1 + x -> fp16 conversion
__global__ __launch_bounds__(256) void k_router(const float* __restrict__ x,
        const float* __restrict__ wr, const float* __restrict__ br){
    int t = blockIdx.x;
    const float4* xr = (const float4*)(x + (size_t)t*HH);
    const float4* wv = (const float4*)wr;
    __half2* xo = (__half2*)(g_xh + (size_t)t*HH);
    float s = 0.f, comp = 0.f, ssq = 0.f;
    #pragma unroll
    for (int q = 0; q < 2; q++){
        int i = threadIdx.x + q*256;                 // 512 float4 per row
        float4 v = xr[i]; float4 w = wv[i];
        float p = v.x*w.x + v.y*w.y + v.z*w.z + v.w*w.w;
        float yk = p - comp; float tk = s + yk; comp = (tk - s) - yk; s = tk;
        ssq += v.x*v.x + v.y*v.y + v.z*v.z + v.w*v.w;
        xo[i*2]   = __floats2half2_rn(v.x, v.y);
        xo[i*2+1] = __floats2half2_rn(v.z, v.w);
    }
    __shared__ float sd[256], sf[256];
    sd[threadIdx.x] = s; sf[threadIdx.x] = ssq;
    __syncthreads();
    for (int o = 128; o > 0; o >>= 1){
        if (threadIdx.x < o){ sd[threadIdx.x] += sd[threadIdx.x+o]; sf[threadIdx.x] += sf[threadIdx.x+o]; }
        __syncthreads();
    }
    if (threadIdx.x == 0){
        g_logits[t] = sd[0] + br[0];
        g_r1[t]     = rsqrtf(sf[0]*(1.f/HH) + EPS_F);
    }
}

__global__ __launch_bounds__(1024) void k_topk(){
    __shared__ float s[SS];
    int b = blockIdx.x, tid = threadIdx.x;
    if (b == 0 && tid == 0) g_nsel = 0;      // folded k_zero
    for (int i = tid; i < SS; i += 1024) s[i] = g_logits[b*SS + i];
    __syncthreads();
    for (int k = 2; k <= SS; k <<= 1){
        for (int j = k >> 1; j > 0; j >>= 1){
            for (int i = tid; i < SS; i += 1024){
                int ixj = i ^ j;
                if (ixj > i){
                    float a = s[i], c = s[ixj];
                    bool up = ((i & k) == 0);
                    if ((a > c) == up){ s[i] = c; s[ixj] = a; }
                }
            }
            __syncthreads();
        }
    }
    if (tid == 0) g_thr[b] = s[SS/2];
}

__global__ __launch_bounds__(256) void k_compact(){
    int t = blockIdx.x*256 + threadIdx.x;
    if (t < BSZ && g_logits[t] >= g_thr[t/SS]){
        int p = atomicAdd(&g_nsel, 1);
        g_sel[p] = t;
    }
}

// out rows for NON-selected tokens = x rows (selected rows written by tk_down)
__global__ __launch_bounds__(256) void k_passthru(const float* __restrict__ x,
        float* __restrict__ out){
    int i = blockIdx.x*256 + threadIdx.x;          // float4 index, HH/4=512/row
    int t = i >> 9;
    if (g_logits[t] < g_thr[t/SS])
        ((float4*)out)[i] = ((const float4*)x)[i];
}

// finalize r2 from 64 deterministic partials per selected row
__global__ __launch_bounds__(256) void k_r2fin(){
    int j = blockIdx.x*256 + threadIdx.x;
    if (j >= g_nsel) return;
    const float* p = &g_ssqp[(size_t)j*64];
    float s = 0.f;
    #pragma unroll
    for (int q = 0; q < 64; q++) s += p[q];
    g_r2[j] = rsqrtf(s*(1.f/HH) + EPS_F);
}

// g_wvh[m][k] = fp16(n1w[m] * Wv[m][k])
__global__ __launch_bounds__(256) void k_scalewv(const float* __restrict__ Wv,
        const float* __restrict__ n1w){
    int i = blockIdx.x*256 + threadIdx.x;          // float4 index
    int row = i >> 9;
    float s = n1w[row];
    float4 v = ((const float4*)Wv)[i];
    __half2* o = (__half2*)(g_wvh + (size_t)i*4);
    o[0] = __floats2half2_rn(v.x*s, v.y*s);
    o[1] = __floats2half2_rn(v.z*s, v.w*s);
}

// transpose in[R][C] -> out[C][R], value fp16(in[r][c] * (scale? scale[r]:1))
__global__ __launch_bounds__(256) void k_transpose(const float* __restrict__ in,
        __half* __restrict__ out, int R, int C, const float* __restrict__ scale){
    __shared__ float ts[32][33];
    int c0 = blockIdx.x*32, r0 = blockIdx.y*32;
    int tx = threadIdx.x, ty = threadIdx.y;       // 32 x 8
    #pragma unroll
    for (int i = 0; i < 32; i += 8){
        int r = r0 + ty + i;
        float v = in[(size_t)r*C + c0 + tx];
        if (scale) v *= scale[r];
        ts[ty+i][tx] = v;
    }
    __syncthreads();
    #pragma unroll
    for (int i = 0; i < 32; i += 8){
        int c = c0 + ty + i;
        out[(size_t)c*R + r0 + tx] = __float2half(ts[tx][ty+i]);
    }
}

// ====================== mma.sync fp16 GEMM kernels =========================

// WcT[n][m] = sum_k Wo^T[n][k] * Wv'[m][k]
__global__ __launch_bounds__(256, 2) void tk_wcomb(){
    int y0 = blockIdx.y*128, x0 = blockIdx.x*128;
    GEMM_PROLOG();
    const __half* aP = g_woT + (size_t)(y0+row)*HH + h16;
    const __half* bP = g_wvh + (size_t)(x0+row)*HH + h16;
    gemm_ml(acc, aP, bP, HH/32, sb, tid);
    EPI_VARS();
    #pragma unroll
    for (int i = 0; i < 4; i++)
        #pragma unroll
        for (int h = 0; h < 2; h++){
            int r = y0 + mB + i*16 + (lane>>2) + h*8;
            #pragma unroll
            for (int j = 0; j < 4; j++){
                int c = x0 + nB + j*8 + (lane&3)*2;
                *(__half2*)&g_WcT[(size_t)r*HH + c] =
                    __floats2half2_rn(acc[i][j][h*2], acc[i][j][h*2+1]);
            }
        }
}

// res = x_sel + r1*(xh_sel @ Wcomb); also emits per-row partial ssq for r2
__global__ __launch_bounds__(256, 2) void tk_attn(const float* __restrict__ x){
    int nsel = g_nsel;
    int m0 = blockIdx.y*128; if (m0 >= nsel) return;
    int n0 = blockIdx.x*128;
    GEMM_PROLOG();
    int ja = m0 + row; if (ja >= nsel) ja = nsel - 1;
    const __half* aP = g_xh  + (size_t)g_sel[ja]*HH + h16;
    const __half* bP = g_WcT + (size_t)(n0+row)*HH + h16;
    gemm_ml(acc, aP, bP, HH/32, sb, tid);
    EPI_VARS();
    int slot = blockIdx.x*4 + ((tid >> 5) & 3);    // nCTA*4 + n-warp
    #pragma unroll
    for (int i = 0; i < 4; i++)
        #pragma unroll
        for (int h = 0; h < 2; h++){
            int j = m0 + mB + i*16 + (lane>>2) + h*8;
            bool act = (j < nsel);
            int tok = act ? g_sel[j] : 0;
            float r1v = act ? g_r1[tok] : 0.f;
            float lssq = 0.f;
            #pragma unroll
            for (int jj = 0; jj < 4; jj++){
                int c = n0 + nB + jj*8 + (lane&3)*2;
                float v0 = 0.f, v1 = 0.f;
                if (act){
                    size_t ob = (size_t)j*HH + c, xb = (size_t)tok*HH + c;
                    v0 = x[xb]   + r1v*acc[i][jj][h*2];
                    v1 = x[xb+1] + r1v*acc[i][jj][h*2+1];
                    g_res[ob]   = v0;  g_res[ob+1]  = v1;
                    *(__half2*)&g_resh[ob] = __floats2half2_rn(v0, v1);
                }
                lssq += v0*v0 + v1*v1;
            }
            lssq += __shfl_xor_sync(0xffffffffu, lssq, 1);
            lssq += __shfl_xor_sync(0xffffffffu, lssq, 2);
            if (act && (lane & 3) == 0)
                g_ssqp[(size_t)j*64 + slot] = lssq;
        }
}

// gate: g_hbuf = silu(r2 * (resh @ wgT'))
__global__ __launch_bounds__(256, 2) void tk_gate(){
    int nsel = g_nsel;
    int m0 = blockIdx.y*128; if (m0 >= nsel) return;
    int n0 = blockIdx.x*128;
    GEMM_PROLOG();
    int ja = m0 + row; if (ja >= nsel) ja = nsel - 1;
    const __half* aP = g_resh + (size_t)ja*HH + h16;
    const __half* bP = g_wgT  + (size_t)(n0+row)*HH + h16;
    gemm_ml(acc, aP, bP, HH/32, sb, tid);
    EPI_VARS();
    #pragma unroll
    for (int i = 0; i < 4; i++)
        #pragma unroll
        for (int h = 0; h < 2; h++){
            int j = m0 + mB + i*16 + (lane>>2) + h*8;
            if (j >= nsel) continue;
            float r2v = g_r2[j];
            #pragma unroll
            for (int jj = 0; jj < 4; jj++){
                int c = n0 + nB + jj*8 + (lane&3)*2;
                size_t ob = (size_t)j*DFFC + c;
                float z0 = r2v*acc[i][jj][h*2];
                float z1 = r2v*acc[i][jj][h*2+1];
                *(__half2*)&g_hbuf[ob] = __floats2half2_rn(
                    z0 / (1.f + expf(-z0)), z1 / (1.f + expf(-z1)));
            }
        }
}

// up + combine: g_hbuf = fp16( g_hbuf * (r2 * (resh @ wuT')) )
__global__ __launch_bounds__(256, 2) void tk_up(){
    int nsel = g_nsel;
    int m0 = blockIdx.y*128; if (m0 >= nsel) return;
    int n0 = blockIdx.x*128;
    GEMM_PROLOG();
    int ja = m0 + row; if (ja >= nsel) ja = nsel - 1;
    const __half* aP = g_resh + (size_t)ja*HH + h16;
    const __half* bP = g_wuT  + (size_t)(n0+row)*HH + h16;
    gemm_ml(acc, aP, bP, HH/32, sb, tid);
    EPI_VARS();
    #pragma unroll
    for (int i = 0; i < 4; i++)
        #pragma unroll
        for (int h = 0; h < 2; h++){
            int j = m0 + mB + i*16 + (lane>>2) + h*8;
            if (j >= nsel) continue;
            float r2v = g_r2[j];
            #pragma unroll
            for (int jj = 0; jj < 4; jj++){
                int c = n0 + nB + jj*8 + (lane&3)*2;
                size_t ob = (size_t)j*DFFC + c;
                float2 gv = __half22float2(*(__half2*)&g_hbuf[ob]);
                float z0 = r2v*acc[i][jj][h*2];
                float z1 = r2v*acc[i][jj][h*2+1];
                *(__half2*)&g_hbuf[ob] = __floats2half2_rn(gv.x*z0, gv.y*z1);
            }
        }
}

// out[sel] = res + hbuf @ wdT'   (K = 8192)
__global__ __launch_bounds__(256, 2) void tk_down(float* __restrict__ out){
    int nsel = g_nsel;
    int m0 = blockIdx.y*128; if (m0 >= nsel) return;
    int n0 = blockIdx.x*128;
    GEMM_PROLOG();
    int ja = m0 + row; if (ja >= nsel) ja = nsel - 1;
    const __half* aP = g_hbuf + (size_t)ja*DFFC + h16;
    const __half* bP = g_wdT  + (size_t)(n0+row)*DFFC + h16;
    gemm_ml(acc, aP, bP, DFFC/32, sb, tid);
    EPI_VARS();
    #pragma unroll
    for (int i = 0; i < 4; i++)
        #pragma unroll
        for (int h = 0; h < 2; h++){
            int j = m0 + mB + i*16 + (lane>>2) + h*8;
            if (j >= nsel) continue;
            int tok = g_sel[j];
            #pragma unroll
            for (int jj = 0; jj < 4; jj++){
                int c = n0 + nB + jj*8 + (lane&3)*2;
                size_t rb = (size_t)j*HH + c, ob = (size_t)tok*HH + c;
                out[ob]   = g_res[rb]   + acc[i][jj][h*2];
                out[ob+1] = g_res[rb+1] + acc[i][jj][h*2+1];
            }
        }
}

// ---------------- launch ----------------------------------------------------
extern "C" void kernel_launch(void* const* d_in, const int* in_sizes, int n_in,
                              void* d_out, int out_size){
    const float* x   = (const float*)d_in[0];
    const float* wr  = (const float*)d_in[1];
    const float* br  = (const float*)d_in[2];
    // d_in[3] = Wq, d_in[4] = Wk : dead (softmax over size-1 axis == 1)
    const float* Wv  = (const float*)d_in[5];
    const float* Wo  = (const float*)d_in[6];
    const float* wg  = (const float*)d_in[7];
    const float* wu  = (const float*)d_in[8];
    const float* wd  = (const float*)d_in[9];
    const float* n1w = (const float*)d_in[10];
    const float* n2w = (const float*)d_in[11];
    float* out = (float*)d_out;

    // side streams/events: host-side resources, created once (first call is
    // the uncaptured correctness run).
    static cudaStream_t s1 = [](){ cudaStream_t s; cudaStreamCreateWithFlags(&s, cudaStreamNonBlocking); return s; }();
    static cudaStream_t s2 = [](){ cudaStream_t s; cudaStreamCreateWithFlags(&s, cudaStreamNonBlocking); return s; }();
    static cudaEvent_t e0 = [](){ cudaEvent_t e; cudaEventCreateWithFlags(&e, cudaEventDisableTiming); return e; }();
    static cudaEvent_t e1 = [](){ cudaEvent_t e; cudaEventCreateWithFlags(&e, cudaEventDisableTiming); return e; }();
    static cudaEvent_t e2 = [](){ cudaEvent_t e; cudaEventCreateWithFlags(&e, cudaEventDisableTiming); return e; }();
    static cudaEvent_t e3 = [](){ cudaEvent_t e; cudaEventCreateWithFlags(&e, cudaEventDisableTiming); return e; }();

    cudaFuncSetAttribute(tk_wcomb, cudaFuncAttributeMaxDynamicSharedMemorySize, SMEM_BYTES);
    cudaFuncSetAttribute(tk_attn,  cudaFuncAttributeMaxDynamicSharedMemorySize, SMEM_BYTES);
    cudaFuncSetAttribute(tk_gate,  cudaFuncAttributeMaxDynamicSharedMemorySize, SMEM_BYTES);
    cudaFuncSetAttribute(tk_up,    cudaFuncAttributeMaxDynamicSharedMemorySize, SMEM_BYTES);
    cudaFuncSetAttribute(tk_down,  cudaFuncAttributeMaxDynamicSharedMemorySize, SMEM_BYTES);

    __half* woT_p; cudaGetSymbolAddress((void**)&woT_p, g_woT);
    __half* wgT_p; cudaGetSymbolAddress((void**)&wgT_p, g_wgT);
    __half* wuT_p; cudaGetSymbolAddress((void**)&wuT_p, g_wuT);
    __half* wdT_p; cudaGetSymbolAddress((void**)&wdT_p, g_wdT);

    // fork
    cudaEventRecord(e0, 0);
    cudaStreamWaitEvent(s1, e0, 0);
    cudaStreamWaitEvent(s2, e0, 0);

    // s1: routing chain (router also produces g_xh) -> e1; passthru off-path
    k_router  <<<BSZ, 256, 0, s1>>>(x, wr, br);
    k_topk    <<<Bb, 1024, 0, s1>>>();
    k_compact <<<BSZ/256, 256, 0, s1>>>();
    cudaEventRecord(e1, s1);
    k_passthru<<<BSZ*HH/4/256, 256, 0, s1>>>(x, out);
    cudaEventRecord(e3, s1);

    // s2: big weight transposes (only needed by gate/up/down) -> e2
    k_transpose<<<dim3(DFFC/32, HH/32),  dim3(32,8), 0, s2>>>(wg, wgT_p, HH, DFFC, n2w);
    k_transpose<<<dim3(DFFC/32, HH/32),  dim3(32,8), 0, s2>>>(wu, wuT_p, HH, DFFC, n2w);
    k_transpose<<<dim3(HH/32, DFFC/32),  dim3(32,8), 0, s2>>>(wd, wdT_p, DFFC, HH, nullptr);
    cudaEventRecord(e2, s2);

    // stream 0: Wcomb chain (selection-independent)
    k_scalewv  <<<(HH*HH/4)/256, 256>>>(Wv, n1w);
    k_transpose<<<dim3(HH/32, HH/32), dim3(32,8)>>>(Wo, woT_p, HH, HH, nullptr);
    tk_wcomb   <<<dim3(16, 16), 256, SMEM_BYTES>>>();

    // attn waits only on routing chain (e1); transposes still running on s2
    cudaStreamWaitEvent(0, e1, 0);
    tk_attn <<<dim3(16, 128), 256, SMEM_BYTES>>>(x);
    k_r2fin <<<BSZ/2/256, 256>>>();

    // FFN needs the transposed weights
    cudaStreamWaitEvent(0, e2, 0);
    tk_gate <<<dim3(64, 128), 256, SMEM_BYTES>>>();
    tk_up   <<<dim3(64, 128), 256, SMEM_BYTES>>>();
    tk_down <<<dim3(16, 128), 256, SMEM_BYTES>>>(out);

    // join passthru before graph end
    cudaStreamWaitEvent(0, e3, 0);
}

// round 14
// speedup vs baseline: 1.0099x; 1.0099x over previous
#include <cuda_runtime.h>
#include <cuda_fp16.h>
#include <math.h>
#include <stdint.h>

// Problem constants
#define Bb   4
#define SS   4096
#define HH   2048
#define DFFC 8192
#define BSZ  (Bb*SS)          // 16384 tokens
#define EPS_F 1e-5f

// ---------------- scratch (device globals; no allocation allowed) ----------
__device__ float g_logits[BSZ];
__device__ float g_r1[BSZ];
__device__ float g_thr[Bb];
__device__ int   g_sel[BSZ];
__device__ int   g_nsel;
__device__ float g_r2[BSZ];
__device__ float g_ssqp[(size_t)BSZ*64];      // per-(nCTA,warp) partial ssq of res

__device__ __half g_xh  [(size_t)BSZ*HH];     // x rounded to fp16
__device__ __half g_wvh [(size_t)HH*HH];      // n1w[m]*Wv fp16        [m][k]
__device__ __half g_woT [(size_t)HH*HH];      // Wo^T fp16             [n][k]
__device__ __half g_WcT [(size_t)HH*HH];      // Wcomb^T fp16          [n][k]
__device__ __half g_wgT [(size_t)DFFC*HH];    // (diag(n2w)*w_gate)^T  [n][k]
__device__ __half g_wuT [(size_t)DFFC*HH];    // (diag(n2w)*w_up)^T    [n][k]
__device__ __half g_wdT [(size_t)HH*DFFC];    // w_down^T fp16         [n][k]
__device__ float  g_res [(size_t)BSZ*HH];     // residual fp32 (selected order)
__device__ __half g_resh[(size_t)BSZ*HH];     // residual fp16
__device__ __half g_hbuf[(size_t)BSZ*DFFC];   // silu(gate) then h (fp16)

// ============================ PTX helpers ==================================
__device__ __forceinline__ uint32_t smem_to_u32(const void* p){
    uint32_t a;
    asm("{ .reg .u64 t; cvta.to.shared.u64 t, %1; cvt.u32.u64 %0, t; }" : "=r"(a) : "l"(p));
    return a;
}
__device__ __forceinline__ void cp16(uint32_t s, const void* g){
    asm volatile("cp.async.cg.shared.global [%0], [%1], 16;" :: "r"(s), "l"(g));
}
#define CP_COMMIT() asm volatile("cp.async.commit_group;" ::: "memory")
#define CP_WAIT1()  asm volatile("cp.async.wait_group 1;" ::: "memory")
#define CP_WAIT0()  asm volatile("cp.async.wait_group 0;" ::: "memory")

#define LDSM4(r, addr) \
    asm volatile("ldmatrix.sync.aligned.m8n8.x4.shared.b16 {%0,%1,%2,%3}, [%4];" \
        : "=r"((r)[0]), "=r"((r)[1]), "=r"((r)[2]), "=r"((r)[3]) : "r"(addr))

__device__ __forceinline__ void mma16n8k16(float* c, const uint32_t* a, const uint32_t* b){
    asm volatile("mma.sync.aligned.m16n8k16.row.col.f32.f16.f16.f32 "
        "{%0,%1,%2,%3},{%4,%5,%6,%7},{%8,%9},{%0,%1,%2,%3};"
        : "+f"(c[0]), "+f"(c[1]), "+f"(c[2]), "+f"(c[3])
        : "r"(a[0]), "r"(a[1]), "r"(a[2]), "r"(a[3]), "r"(b[0]), "r"(b[1]));
}

// ===================== GEMM mainloop (128x128, K-stage 32 halves) ==========
// 256 threads = 8 warps in 2x4 (m x n); warp tile 64x32; acc[4 mtile][4 ntile][4]
// SMEM per stage block (20480B): A rows 128 x 80B at [0,10240), B at [10240,20480).
// 80B row stride -> ldmatrix 8-row fetches hit 32 distinct banks, conflict-free.
// 3-stage cp.async pipeline (PROVEN best: R9/R11), ONE sync/stage.
#define STAGEB  20480
#define NSTAGE  3
#define SMEM_BYTES (NSTAGE*STAGEB)

__device__ __forceinline__ void gemm_ml(float (&acc)[4][4][4],
        const __half* aP, const __half* bP, int nK32,
        uint32_t sb, int tid)
{
    int lane = tid & 31;
    int mW = (tid >> 7) * 64;
    int nW = ((tid >> 5) & 3) * 32;
    uint32_t cpA = sb + (tid >> 1)*80 + (tid & 1)*32;
    uint32_t cpB = cpA + 10240;
    uint32_t aoff = (uint32_t)(mW + (lane & 7) + ((lane >> 3) & 1)*8)*80 + (lane >> 4)*16;
    uint32_t boff = 10240u + (uint32_t)(nW + ((lane >> 4) & 1)*8 + (lane & 7))*80
                          + ((lane >> 3) & 1)*16;

    #pragma unroll
    for (int s = 0; s < 2; s++){
        uint32_t off = s*STAGEB;
        const __half* an = aP + s*32;
        const __half* bn = bP + s*32;
        cp16(cpA + off, an); cp16(cpA + off + 16, an + 8);
        cp16(cpB + off, bn); cp16(cpB + off + 16, bn + 8);
        CP_COMMIT();
    }

    #pragma unroll 1
    for (int s = 0; s < nK32; s++){
        if (s + 1 < nK32) CP_WAIT1(); else CP_WAIT0();
        __syncthreads();
        if (s + 2 < nK32){
            uint32_t off = ((uint32_t)(s + 2) % NSTAGE)*STAGEB;
            const __half* an = aP + (s + 2)*32;
            const __half* bn = bP + (s + 2)*32;
            cp16(cpA + off, an); cp16(cpA + off + 16, an + 8);
            cp16(cpB + off, bn); cp16(cpB + off + 16, bn + 8);
            CP_COMMIT();
        }
        uint32_t st = ((uint32_t)s % NSTAGE)*STAGEB;
        uint32_t smA = sb + st + aoff;
        uint32_t smB = sb + st + boff;
        #pragma unroll
        for (int step = 0; step < 2; step++){
            uint32_t a[4][4], b[2][4];
            #pragma unroll
            for (int i = 0; i < 4; i++) LDSM4(a[i], smA + i*1280 + step*32);
            #pragma unroll
            for (int p = 0; p < 2; p++) LDSM4(b[p], smB + p*1280 + step*32);
            #pragma unroll
            for (int i = 0; i < 4; i++)
                #pragma unroll
                for (int j = 0; j < 4; j++)
                    mma16n8k16(acc[i][j], a[i], &b[j >> 1][(j & 1)*2]);
        }
    }
}

#define GEMM_PROLOG() \
    extern __shared__ float smf[]; \
    uint32_t sb = smem_to_u32(smf); \
    int tid = threadIdx.x; \
    int row = tid >> 1, h16 = (tid & 1) * 16; \
    float acc[4][4][4]; \
    _Pragma("unroll") for (int i = 0; i < 4; i++) \
    _Pragma("unroll") for (int j = 0; j < 4; j++) \
    _Pragma("unroll") for (int q = 0; q < 4; q++) acc[i][j][q] = 0.f;

#define EPI_VARS() \
    int lane = tid & 31; \
    int mB = (tid >> 7) * 64; \
    int nB = ((tid >> 5) & 3) * 32;

// =========================== small kernels =================================
// fused: router logits (fp32 Kahan) + rms1 + x -> fp16 conversion
__global__ __launch_bounds__(256) void k_router(const float* __restrict__ x,
        const float* __restrict__ wr, const float* __restrict__ br){
    int t = blockIdx.x;
    const float4* xr = (const float4*)(x + (size_t)t*HH);
    const float4* wv = (const float4*)wr;
    __half2* xo = (__half2*)(g_xh + (size_t)t*HH);
    float s = 0.f, comp = 0.f, ssq = 0.f;
    #pragma unroll
    for (int q = 0; q < 2; q++){
        int i = threadIdx.x + q*256;                 // 512 float4 per row
        float4 v = xr[i]; float4 w = wv[i];
        float p = v.x*w.x + v.y*w.y + v.z*w.z + v.w*w.w;
        float yk = p - comp; float tk = s + yk; comp = (tk - s) - yk; s = tk;
        ssq += v.x*v.x + v.y*v.y + v.z*v.z + v.w*v.w;
        xo[i*2]   = __floats2half2_rn(v.x, v.y);
        xo[i*2+1] = __floats2half2_rn(v.z, v.w);
    }
    __shared__ float sd[256], sf[256];
    sd[threadIdx.x] = s; sf[threadIdx.x] = ssq;
    __syncthreads();
    for (int o = 128; o > 0; o >>= 1){
        if (threadIdx.x < o){ sd[threadIdx.x] += sd[threadIdx.x+o]; sf[threadIdx.x] += sf[threadIdx.x+o]; }
        __syncthreads();
    }
    if (threadIdx.x == 0){
        g_logits[t] = sd[0] + br[0];
        g_r1[t]     = rsqrtf(sf[0]*(1.f/HH) + EPS_F);
    }
}

__global__ __launch_bounds__(1024) void k_topk(){
    __shared__ float s[SS];
    int b = blockIdx.x, tid = threadIdx.x;
    if (b == 0 && tid == 0) g_nsel = 0;      // folded k_zero
    for (int i = tid; i < SS; i += 1024) s[i] = g_logits[b*SS + i];
    __syncthreads();
    for (int k = 2; k <= SS; k <<= 1){
        for (int j = k >> 1; j > 0; j >>= 1){
            for (int i = tid; i < SS; i += 1024){
                int ixj = i ^ j;
                if (ixj > i){
                    float a = s[i], c = s[ixj];
                    bool up = ((i & k) == 0);
                    if ((a > c) == up){ s[i] = c; s[ixj] = a; }
                }
            }
            __syncthreads();
        }
    }
    if (tid == 0) g_thr[b] = s[SS/2];
}

__global__ __launch_bounds__(256) void k_compact(){
    int t = blockIdx.x*256 + threadIdx.x;
    if (t < BSZ && g_logits[t] >= g_thr[t/SS]){
        int p = atomicAdd(&g_nsel, 1);
        g_sel[p] = t;
    }
}

// out rows for NON-selected tokens = x rows (selected rows written by tk_down)
__global__ __launch_bounds__(256) void k_passthru(const float* __restrict__ x,
        float* __restrict__ out){
    int i = blockIdx.x*256 + threadIdx.x;          // float4 index, HH/4=512/row
    int t = i >> 9;
    if (g_logits[t] < g_thr[t/SS])
        ((float4*)out)[i] = ((const float4*)x)[i];
}

// finalize r2 from 64 deterministic partials per selected row
__global__ __launch_bounds__(256) void k_r2fin(){
    int j = blockIdx.x*256 + threadIdx.x;
    if (j >= g_nsel) return;
    const float* p = &g_ssqp[(size_t)j*64];
    float s = 0.f;
    #pragma unroll
    for (int q = 0; q < 64; q++) s += p[q];
    g_r2[j] = rsqrtf(s*(1.f/HH) + EPS_F);
}

// g_wvh[m][k] = fp16(n1w[m] * Wv[m][k])
__global__ __launch_bounds__(256) void k_scalewv(const float* __restrict__ Wv,
        const float* __restrict__ n1w){
    int i = blockIdx.x*256 + threadIdx.x;          // float4 index
    int row = i >> 9;
    float s = n1w[row];
    float4 v = ((const float4*)Wv)[i];
    __half2* o = (__half2*)(g_wvh + (size_t)i*4);
    o[0] = __floats2half2_rn(v.x*s, v.y*s);
    o[1] = __floats2half2_rn(v.z*s, v.w*s);
}

// transpose in[R][C] -> out[C][R], value fp16(in[r][c] * (scale? scale[r]:1))
__global__ __launch_bounds__(256) void k_transpose(const float* __restrict__ in,
        __half* __restrict__ out, int R, int C, const float* __restrict__ scale){
    __shared__ float ts[32][33];
    int c0 = blockIdx.x*32, r0 = blockIdx.y*32;
    int tx = threadIdx.x, ty = threadIdx.y;       // 32 x 8
    #pragma unroll
    for (int i = 0; i < 32; i += 8){
        int r = r0 + ty + i;
        float v = in[(size_t)r*C + c0 + tx];
        if (scale) v *= scale[r];
        ts[ty+i][tx] = v;
    }
    __syncthreads();
    #pragma unroll
    for (int i = 0; i < 32; i += 8){
        int c = c0 + ty + i;
        out[(size_t)c*R + r0 + tx] = __float2half(ts[tx][ty+i]);
    }
}

// ====================== mma.sync fp16 GEMM kernels =========================

// WcT[n][m] = sum_k Wo^T[n][k] * Wv'[m][k]
__global__ __launch_bounds__(256, 2) void tk_wcomb(){
    int y0 = blockIdx.y*128, x0 = blockIdx.x*128;
    GEMM_PROLOG();
    const __half* aP = g_woT + (size_t)(y0+row)*HH + h16;
    const __half* bP = g_wvh + (size_t)(x0+row)*HH + h16;
    gemm_ml(acc, aP, bP, HH/32, sb, tid);
    EPI_VARS();
    #pragma unroll
    for (int i = 0; i < 4; i++)
        #pragma unroll
        for (int h = 0; h < 2; h++){
            int r = y0 + mB + i*16 + (lane>>2) + h*8;
            #pragma unroll
            for (int j = 0; j < 4; j++){
                int c = x0 + nB + j*8 + (lane&3)*2;
                *(__half2*)&g_WcT[(size_t)r*HH + c] =
                    __floats2half2_rn(acc[i][j][h*2], acc[i][j][h*2+1]);
            }
        }
}

// res = x_sel + r1*(xh_sel @ Wcomb); also emits per-row partial ssq for r2
__global__ __launch_bounds__(256, 2) void tk_attn(const float* __restrict__ x){
    int nsel = g_nsel;
    int m0 = blockIdx.y*128; if (m0 >= nsel) return;
    int n0 = blockIdx.x*128;
    GEMM_PROLOG();
    int ja = m0 + row; if (ja >= nsel) ja = nsel - 1;
    const __half* aP = g_xh  + (size_t)g_sel[ja]*HH + h16;
    const __half* bP = g_WcT + (size_t)(n0+row)*HH + h16;
    gemm_ml(acc, aP, bP, HH/32, sb, tid);
    EPI_VARS();
    int slot = blockIdx.x*4 + ((tid >> 5) & 3);    // nCTA*4 + n-warp
    #pragma unroll
    for (int i = 0; i < 4; i++)
        #pragma unroll
        for (int h = 0; h < 2; h++){
            int j = m0 + mB + i*16 + (lane>>2) + h*8;
            bool act = (j < nsel);
            int tok = act ? g_sel[j] : 0;
            float r1v = act ? g_r1[tok] : 0.f;
            float lssq = 0.f;
            #pragma unroll
            for (int jj = 0; jj < 4; jj++){
                int c = n0 + nB + jj*8 + (lane&3)*2;
                float v0 = 0.f, v1 = 0.f;
                if (act){
                    size_t ob = (size_t)j*HH + c, xb = (size_t)tok*HH + c;
                    v0 = x[xb]   + r1v*acc[i][jj][h*2];
                    v1 = x[xb+1] + r1v*acc[i][jj][h*2+1];
                    g_res[ob]   = v0;  g_res[ob+1]  = v1;
                    *(__half2*)&g_resh[ob] = __floats2half2_rn(v0, v1);
                }
                lssq += v0*v0 + v1*v1;
            }
            lssq += __shfl_xor_sync(0xffffffffu, lssq, 1);
            lssq += __shfl_xor_sync(0xffffffffu, lssq, 2);
            if (act && (lane & 3) == 0)
                g_ssqp[(size_t)j*64 + slot] = lssq;
        }
}

// gate: g_hbuf = silu(r2 * (resh @ wgT'))
__global__ __launch_bounds__(256, 2) void tk_gate(){
    int nsel = g_nsel;
    int m0 = blockIdx.y*128; if (m0 >= nsel) return;
    int n0 = blockIdx.x*128;
    GEMM_PROLOG();
    int ja = m0 + row; if (ja >= nsel) ja = nsel - 1;
    const __half* aP = g_resh + (size_t)ja*HH + h16;
    const __half* bP = g_wgT  + (size_t)(n0+row)*HH + h16;
    gemm_ml(acc, aP, bP, HH/32, sb, tid);
    EPI_VARS();
    #pragma unroll
    for (int i = 0; i < 4; i++)
        #pragma unroll
        for (int h = 0; h < 2; h++){
            int j = m0 + mB + i*16 + (lane>>2) + h*8;
            if (j >= nsel) continue;
            float r2v = g_r2[j];
            #pragma unroll
            for (int jj = 0; jj < 4; jj++){
                int c = n0 + nB + jj*8 + (lane&3)*2;
                size_t ob = (size_t)j*DFFC + c;
                float z0 = r2v*acc[i][jj][h*2];
                float z1 = r2v*acc[i][jj][h*2+1];
                *(__half2*)&g_hbuf[ob] = __floats2half2_rn(
                    z0 / (1.f + expf(-z0)), z1 / (1.f + expf(-z1)));
            }
        }
}

// up + combine: g_hbuf = fp16( g_hbuf * (r2 * (resh @ wuT')) )
__global__ __launch_bounds__(256, 2) void tk_up(){
    int nsel = g_nsel;
    int m0 = blockIdx.y*128; if (m0 >= nsel) return;
    int n0 = blockIdx.x*128;
    GEMM_PROLOG();
    int ja = m0 + row; if (ja >= nsel) ja = nsel - 1;
    const __half* aP = g_resh + (size_t)ja*HH + h16;
    const __half* bP = g_wuT  + (size_t)(n0+row)*HH + h16;
    gemm_ml(acc, aP, bP, HH/32, sb, tid);
    EPI_VARS();
    #pragma unroll
    for (int i = 0; i < 4; i++)
        #pragma unroll
        for (int h = 0; h < 2; h++){
            int j = m0 + mB + i*16 + (lane>>2) + h*8;
            if (j >= nsel) continue;
            float r2v = g_r2[j];
            #pragma unroll
            for (int jj = 0; jj < 4; jj++){
                int c = n0 + nB + jj*8 + (lane&3)*2;
                size_t ob = (size_t)j*DFFC + c;
                float2 gv = __half22float2(*(__half2*)&g_hbuf[ob]);
                float z0 = r2v*acc[i][jj][h*2];
                float z1 = r2v*acc[i][jj][h*2+1];
                *(__half2*)&g_hbuf[ob] = __floats2half2_rn(gv.x*z0, gv.y*z1);
            }
        }
}

// out[sel] = res + hbuf @ wdT'   (K = 8192)
__global__ __launch_bounds__(256, 2) void tk_down(float* __restrict__ out){
    int nsel = g_nsel;
    int m0 = blockIdx.y*128; if (m0 >= nsel) return;
    int n0 = blockIdx.x*128;
    GEMM_PROLOG();
    int ja = m0 + row; if (ja >= nsel) ja = nsel - 1;
    const __half* aP = g_hbuf + (size_t)ja*DFFC + h16;
    const __half* bP = g_wdT  + (size_t)(n0+row)*DFFC + h16;
    gemm_ml(acc, aP, bP, DFFC/32, sb, tid);
    EPI_VARS();
    #pragma unroll
    for (int i = 0; i < 4; i++)
        #pragma unroll
        for (int h = 0; h < 2; h++){
            int j = m0 + mB + i*16 + (lane>>2) + h*8;
            if (j >= nsel) continue;
            int tok = g_sel[j];
            #pragma unroll
            for (int jj = 0; jj < 4; jj++){
                int c = n0 + nB + jj*8 + (lane&3)*2;
                size_t rb = (size_t)j*HH + c, ob = (size_t)tok*HH + c;
                out[ob]   = g_res[rb]   + acc[i][jj][h*2];
                out[ob+1] = g_res[rb+1] + acc[i][jj][h*2+1];
            }
        }
}

// ---------------- launch ----------------------------------------------------
extern "C" void kernel_launch(void* const* d_in, const int* in_sizes, int n_in,
                              void* d_out, int out_size){
    const float* x   = (const float*)d_in[0];
    const float* wr  = (const float*)d_in[1];
    const float* br  = (const float*)d_in[2];
    // d_in[3] = Wq, d_in[4] = Wk : dead (softmax over size-1 axis == 1)
    const float* Wv  = (const float*)d_in[5];
    const float* Wo  = (const float*)d_in[6];
    const float* wg  = (const float*)d_in[7];
    const float* wu  = (const float*)d_in[8];
    const float* wd  = (const float*)d_in[9];
    const float* n1w = (const float*)d_in[10];
    const float* n2w = (const float*)d_in[11];
    float* out = (float*)d_out;

    // side streams/events: host-side resources, created once (first call is
    // the uncaptured correctness run).
    static cudaStream_t s1 = [](){ cudaStream_t s; cudaStreamCreateWithFlags(&s, cudaStreamNonBlocking); return s; }();
    static cudaStream_t s2 = [](){ cudaStream_t s; cudaStreamCreateWithFlags(&s, cudaStreamNonBlocking); return s; }();
    static cudaEvent_t e0 = [](){ cudaEvent_t e; cudaEventCreateWithFlags(&e, cudaEventDisableTiming); return e; }();
    static cudaEvent_t e1 = [](){ cudaEvent_t e; cudaEventCreateWithFlags(&e, cudaEventDisableTiming); return e; }();
    static cudaEvent_t e2 = [](){ cudaEvent_t e; cudaEventCreateWithFlags(&e, cudaEventDisableTiming); return e; }();
    static cudaEvent_t e3 = [](){ cudaEvent_t e; cudaEventCreateWithFlags(&e, cudaEventDisableTiming); return e; }();
    static cudaEvent_t e4 = [](){ cudaEvent_t e; cudaEventCreateWithFlags(&e, cudaEventDisableTiming); return e; }();

    cudaFuncSetAttribute(tk_wcomb, cudaFuncAttributeMaxDynamicSharedMemorySize, SMEM_BYTES);
    cudaFuncSetAttribute(tk_attn,  cudaFuncAttributeMaxDynamicSharedMemorySize, SMEM_BYTES);
    cudaFuncSetAttribute(tk_gate,  cudaFuncAttributeMaxDynamicSharedMemorySize, SMEM_BYTES);
    cudaFuncSetAttribute(tk_up,    cudaFuncAttributeMaxDynamicSharedMemorySize, SMEM_BYTES);
    cudaFuncSetAttribute(tk_down,  cudaFuncAttributeMaxDynamicSharedMemorySize, SMEM_BYTES);

    __half* woT_p; cudaGetSymbolAddress((void**)&woT_p, g_woT);
    __half* wgT_p; cudaGetSymbolAddress((void**)&wgT_p, g_wgT);
    __half* wuT_p; cudaGetSymbolAddress((void**)&wuT_p, g_wuT);
    __half* wdT_p; cudaGetSymbolAddress((void**)&wdT_p, g_wdT);

    // fork
    cudaEventRecord(e0, 0);
    cudaStreamWaitEvent(s1, e0, 0);
    cudaStreamWaitEvent(s2, e0, 0);

    // s1: routing chain (router also produces g_xh) -> e1; passthru off-path
    k_router  <<<BSZ, 256, 0, s1>>>(x, wr, br);
    k_topk    <<<Bb, 1024, 0, s1>>>();
    k_compact <<<BSZ/256, 256, 0, s1>>>();
    cudaEventRecord(e1, s1);
    k_passthru<<<BSZ*HH/4/256, 256, 0, s1>>>(x, out);
    cudaEventRecord(e3, s1);

    // s2: transposeWo first (feeds wcomb; runs concurrently with k_scalewv),
    //     then the big FFN weight transposes -> e2
    k_transpose<<<dim3(HH/32, HH/32),    dim3(32,8), 0, s2>>>(Wo, woT_p, HH, HH, nullptr);
    cudaEventRecord(e4, s2);
    k_transpose<<<dim3(DFFC/32, HH/32),  dim3(32,8), 0, s2>>>(wg, wgT_p, HH, DFFC, n2w);
    k_transpose<<<dim3(DFFC/32, HH/32),  dim3(32,8), 0, s2>>>(wu, wuT_p, HH, DFFC, n2w);
    k_transpose<<<dim3(HH/32, DFFC/32),  dim3(32,8), 0, s2>>>(wd, wdT_p, DFFC, HH, nullptr);
    cudaEventRecord(e2, s2);

    // stream 0: Wcomb chain (selection-independent)
    k_scalewv  <<<(HH*HH/4)/256, 256>>>(Wv, n1w);
    cudaStreamWaitEvent(0, e4, 0);
    tk_wcomb   <<<dim3(16, 16), 256, SMEM_BYTES>>>();

    // attn waits only on routing chain (e1); transposes still running on s2
    cudaStreamWaitEvent(0, e1, 0);
    tk_attn <<<dim3(16, 128), 256, SMEM_BYTES>>>(x);
    k_r2fin <<<BSZ/2/256, 256>>>();

    // FFN needs the transposed weights
    cudaStreamWaitEvent(0, e2, 0);
    tk_gate <<<dim3(64, 128), 256, SMEM_BYTES>>>();
    tk_up   <<<dim3(64, 128), 256, SMEM_BYTES>>>();
    tk_down <<<dim3(16, 128), 256, SMEM_BYTES>>>(out);

    // join passthru before graph end
    cudaStreamWaitEvent(0, e3, 0);
}